// round 10
// baseline (speedup 1.0000x reference)
#include <cuda_runtime.h>
#include <math.h>

// Problem constants
#define R_    2048
#define C_    1024
#define NCH   8
#define NB    128          // grid: must all be co-resident (<=148 SMs)
#define NT    512

// Scratch (no allocations allowed -> device globals)
__device__ float g_lq[R_ * NCH];        // log prod_ba(1-P) per (row,ch)   64KB
__device__ float g_Lp[16 * 8192];       // [rg16][ch*1024+c] partial L    512KB
__device__ float g_dsPart[8 * R_];      // [cq][row] D row-sum quarters    64KB
__device__ float g_pA[64 * NB];         // [i][block] partial sum_r P*s
__device__ float g_pB[64 * NB];         // [i][block] partial sum_r P
__device__ float g_pSel[NB];            // per-block row-sel partials
__device__ float g_ncolB[NB];           // per-block colch sums
__device__ volatile int g_flag[NB];     // barrier flags (epoch; reset at end)

// Flag-array grid barrier: one release-store per block (distinct addresses,
// no RMW contention), warp 0 polls with volatile loads.
__device__ __forceinline__ void grid_barrier(int b, int t, int epoch)
{
    __syncthreads();
    if (t == 0) { __threadfence(); g_flag[b] = epoch; }
    if (t < 32) {
        for (;;) {
            bool ok = true;
            #pragma unroll
            for (int k = 0; k < 4; k++)
                ok &= (g_flag[t + 32 * k] >= epoch);
            if (__all_sync(0xFFFFFFFFu, ok)) break;
            __nanosleep(64);
        }
    }
    __syncthreads();
    __threadfence();   // acquire side
}

// ---------------------------------------------------------------------------
// Single kernel, 128 blocks x 512 threads.
// Output layout: P[131072] | tot[8] | max_nnz[8] | num_col[8] | num_row[8] |
//                nnz_ch_ba[64] | col_density[8] | num_row_sel[1]
// ---------------------------------------------------------------------------
__global__ __launch_bounds__(NT) void k_all(const float* __restrict__ W,
                                            const float* __restrict__ D,
                                            const float* __restrict__ G,
                                            float* __restrict__ out)
{
    __shared__ float sP[16][64];         // P rows of this block (persists)
    __shared__ float sSel[16];
    __shared__ union {
        struct {                          // phase 1
            float  slq[128][NCH];         // 4KB
            float4 sacc[8][256];          // 32KB
        } p1;
        struct {                          // phase 2 + finalize
            float red[8][64];
            float sdsp[16][8];
            float sds2[16];
            float cs[2];
            float snn[64];
            float sps[64];
            float snc[128];
            float ssel;
        } p2;
    } u;

    const int t    = threadIdx.x;
    const int wid  = t >> 5;              // 0..15
    const int lane = t & 31;
    const int b    = blockIdx.x;

    // ================= Phase 0: softmax, 1 row per warp =================
    {
        const int r = b * 16 + wid;
        const float2* W2 = reinterpret_cast<const float2*>(W);
        const float2* G2 = reinterpret_cast<const float2*>(G);
        float2 w  = W2[r * 32 + lane];
        float2 gv = G2[r * 32 + lane];
        float e0 = w.x + gv.x;
        float e1 = w.y + gv.y;

        float m = fmaxf(e0, e1);
        #pragma unroll
        for (int o = 16; o > 0; o >>= 1)
            m = fmaxf(m, __shfl_xor_sync(0xFFFFFFFFu, m, o));

        float x0 = expf(e0 - m);
        float x1 = expf(e1 - m);
        float s  = x0 + x1;
        #pragma unroll
        for (int o = 16; o > 0; o >>= 1)
            s += __shfl_xor_sync(0xFFFFFFFFu, s, o);

        const float inv = 1.0f / s;       // == max(P): exp(0)=1 at the argmax
        const float p0  = x0 * inv;
        const float p1  = x1 * inv;

        reinterpret_cast<float2*>(out)[r * 32 + lane] = make_float2(p0, p1);
        sP[wid][2 * lane]     = p0;
        sP[wid][2 * lane + 1] = p1;

        float lq = log1pf(-p0) + log1pf(-p1);
        lq += __shfl_xor_sync(0xFFFFFFFFu, lq, 1);
        lq += __shfl_xor_sync(0xFFFFFFFFu, lq, 2);
        if ((lane & 3) == 0) g_lq[r * NCH + (lane >> 2)] = lq;
        if (lane == 0) sSel[wid] = (inv > 0.99f) ? 1.0f : 0.0f;
    }
    __syncthreads();

    if (t < 64) {                          // pB partial (16 rows of this block)
        float pb = 0.f;
        #pragma unroll
        for (int rl = 0; rl < 16; rl++) pb += sP[rl][t];
        g_pB[t * NB + b] = pb;
    }
    if (t == 0) {
        float v = 0.f;
        #pragma unroll
        for (int w2 = 0; w2 < 16; w2++) v += sSel[w2];
        g_pSel[b] = v;
    }

    grid_barrier(b, t, 1);

    // ================= Phase 1: D tile (rg, cq) = 128 rows x 128 cols =======
    {
        const int rg = b >> 3;
        const int cq = b & 7;
        const int r0 = rg * 128;

        // stage lq tile: 128 rows x 8 ch = 256 float4, coalesced
        if (t < 256)
            reinterpret_cast<float4*>(&u.p1.slq[0][0])[t] =
                reinterpret_cast<const float4*>(&g_lq[r0 * NCH])[t];
        __syncthreads();

        float acc[NCH][4];
        #pragma unroll
        for (int ch = 0; ch < NCH; ch++)
            #pragma unroll
            for (int k = 0; k < 4; k++) acc[ch][k] = 0.f;
        float dsv[8];

        const float4* D4 = reinterpret_cast<const float4*>(D);
        #pragma unroll
        for (int j = 0; j < 8; j++) {
            const int rl = wid * 8 + j;
            float4 d = D4[(size_t)(r0 + rl) * 256 + cq * 32 + lane];
            dsv[j] = (d.x + d.y) + (d.z + d.w);
            const float4 l0 = *reinterpret_cast<const float4*>(&u.p1.slq[rl][0]);
            const float4 l1 = *reinterpret_cast<const float4*>(&u.p1.slq[rl][4]);
            acc[0][0] = fmaf(d.x, l0.x, acc[0][0]); acc[0][1] = fmaf(d.y, l0.x, acc[0][1]);
            acc[0][2] = fmaf(d.z, l0.x, acc[0][2]); acc[0][3] = fmaf(d.w, l0.x, acc[0][3]);
            acc[1][0] = fmaf(d.x, l0.y, acc[1][0]); acc[1][1] = fmaf(d.y, l0.y, acc[1][1]);
            acc[1][2] = fmaf(d.z, l0.y, acc[1][2]); acc[1][3] = fmaf(d.w, l0.y, acc[1][3]);
            acc[2][0] = fmaf(d.x, l0.z, acc[2][0]); acc[2][1] = fmaf(d.y, l0.z, acc[2][1]);
            acc[2][2] = fmaf(d.z, l0.z, acc[2][2]); acc[2][3] = fmaf(d.w, l0.z, acc[2][3]);
            acc[3][0] = fmaf(d.x, l0.w, acc[3][0]); acc[3][1] = fmaf(d.y, l0.w, acc[3][1]);
            acc[3][2] = fmaf(d.z, l0.w, acc[3][2]); acc[3][3] = fmaf(d.w, l0.w, acc[3][3]);
            acc[4][0] = fmaf(d.x, l1.x, acc[4][0]); acc[4][1] = fmaf(d.y, l1.x, acc[4][1]);
            acc[4][2] = fmaf(d.z, l1.x, acc[4][2]); acc[4][3] = fmaf(d.w, l1.x, acc[4][3]);
            acc[5][0] = fmaf(d.x, l1.y, acc[5][0]); acc[5][1] = fmaf(d.y, l1.y, acc[5][1]);
            acc[5][2] = fmaf(d.z, l1.y, acc[5][2]); acc[5][3] = fmaf(d.w, l1.y, acc[5][3]);
            acc[6][0] = fmaf(d.x, l1.z, acc[6][0]); acc[6][1] = fmaf(d.y, l1.z, acc[6][1]);
            acc[6][2] = fmaf(d.z, l1.z, acc[6][2]); acc[6][3] = fmaf(d.w, l1.z, acc[6][3]);
            acc[7][0] = fmaf(d.x, l1.w, acc[7][0]); acc[7][1] = fmaf(d.y, l1.w, acc[7][1]);
            acc[7][2] = fmaf(d.z, l1.w, acc[7][2]); acc[7][3] = fmaf(d.w, l1.w, acc[7][3]);
        }

        // per-row quarter-sums -> global dsPart
        #pragma unroll
        for (int j = 0; j < 8; j++) {
            float v = dsv[j];
            #pragma unroll
            for (int o = 16; o > 0; o >>= 1)
                v += __shfl_xor_sync(0xFFFFFFFFu, v, o);
            if (lane == 0) g_dsPart[cq * R_ + r0 + wid * 8 + j] = v;
        }

        // two-stage cross-warp acc reduction (32KB buffer)
        if (wid >= 8) {
            #pragma unroll
            for (int ch = 0; ch < NCH; ch++)
                u.p1.sacc[wid - 8][ch * 32 + lane] =
                    make_float4(acc[ch][0], acc[ch][1], acc[ch][2], acc[ch][3]);
        }
        __syncthreads();
        if (wid < 8) {
            #pragma unroll
            for (int ch = 0; ch < NCH; ch++) {
                float4 v = u.p1.sacc[wid][ch * 32 + lane];
                v.x += acc[ch][0]; v.y += acc[ch][1];
                v.z += acc[ch][2]; v.w += acc[ch][3];
                u.p1.sacc[wid][ch * 32 + lane] = v;
            }
        }
        __syncthreads();
        if (t < 256) {
            float4 s = u.p1.sacc[0][t];
            #pragma unroll
            for (int g = 1; g < 8; g++) {
                float4 v = u.p1.sacc[g][t];
                s.x += v.x; s.y += v.y; s.z += v.z; s.w += v.w;
            }
            const int ch = t >> 5, q = t & 31;
            reinterpret_cast<float4*>(g_Lp)[rg * 2048 + ch * 256 + cq * 32 + q] = s;
        }
    }

    grid_barrier(b, t, 2);

    // ================= Phase 2 =================
    // 2a: colch — block b owns outputs o = b*64..b*64+63 (single channel),
    //     16 partials/output, 2 loads per thread.
    {
        const int ol = t & 63;
        const int pg = t >> 6;            // 0..7
        u.p2.red[pg][ol] = g_Lp[(2 * pg) * 8192 + b * 64 + ol]
                         + g_Lp[(2 * pg + 1) * 8192 + b * 64 + ol];
    }
    // 2b: stage dsPart quarters for this block's 16 rows
    if (t < 128) {
        const int cqi = t >> 4, rl = t & 15;
        u.p2.sdsp[rl][cqi] = g_dsPart[cqi * R_ + b * 16 + rl];
    }
    __syncthreads();

    if (t < 64) {
        float L = 0.f;
        #pragma unroll
        for (int k = 0; k < 8; k++) L += u.p2.red[k][t];
        float colch = 1.0f - expf(L);
        #pragma unroll
        for (int o = 16; o > 0; o >>= 1)
            colch += __shfl_xor_sync(0xFFFFFFFFu, colch, o);
        if (lane == 0) u.p2.cs[t >> 5] = colch;
    }
    if (t >= 64 && t < 80) {
        const int rl = t - 64;
        float v = 0.f;
        #pragma unroll
        for (int k = 0; k < 8; k++) v += u.p2.sdsp[rl][k];
        u.p2.sds2[rl] = v;
    }
    __syncthreads();

    if (t < 64) {                          // pA partial (exact s[r] per row)
        float pa = 0.f;
        #pragma unroll
        for (int rl = 0; rl < 16; rl++)
            pa = fmaf(sP[rl][t], u.p2.sds2[rl], pa);
        g_pA[t * NB + b] = pa;
    }
    if (t == 0) g_ncolB[b] = u.p2.cs[0] + u.p2.cs[1];

    // ================= Finalize (block 0) =================
    __syncthreads();
    if (t == 0) { __threadfence(); g_flag[b] = 3; }
    if (b != 0) return;

    if (t < 32) {
        for (;;) {
            bool ok = true;
            #pragma unroll
            for (int k = 0; k < 4; k++)
                ok &= (g_flag[t + 32 * k] >= 3);
            if (__all_sync(0xFFFFFFFFu, ok)) break;
            __nanosleep(64);
        }
    }
    __syncthreads();
    __threadfence();

    // nnz / psum: warp wid reduces outputs i = wid*4 .. wid*4+3
    #pragma unroll
    for (int k = 0; k < 4; k++) {
        const int i = wid * 4 + k;
        float va = g_pA[i * NB + lane]      + g_pA[i * NB + lane + 32]
                 + g_pA[i * NB + lane + 64] + g_pA[i * NB + lane + 96];
        float vb = g_pB[i * NB + lane]      + g_pB[i * NB + lane + 32]
                 + g_pB[i * NB + lane + 64] + g_pB[i * NB + lane + 96];
        #pragma unroll
        for (int o = 16; o > 0; o >>= 1) {
            va += __shfl_xor_sync(0xFFFFFFFFu, va, o);
            vb += __shfl_xor_sync(0xFFFFFFFFu, vb, o);
        }
        if (lane == 0) { u.p2.snn[i] = va; u.p2.sps[i] = vb; }
    }
    if (wid == 0) {                        // sel
        float v = g_pSel[lane]      + g_pSel[lane + 32]
                + g_pSel[lane + 64] + g_pSel[lane + 96];
        #pragma unroll
        for (int o = 16; o > 0; o >>= 1)
            v += __shfl_xor_sync(0xFFFFFFFFu, v, o);
        if (lane == 0) u.p2.ssel = v;
    }
    if (t >= 256 && t < 384) u.p2.snc[t - 256] = g_ncolB[t - 256];
    __syncthreads();

    if (t < 64) out[131104 + t] = u.p2.snn[t];        // nnz_ch_ba

    if (t < NCH) {
        float m = -1e30f, ns = 0.f, rs = 0.f;
        #pragma unroll
        for (int ba = 0; ba < 8; ba++) {
            float nv = u.p2.snn[t * 8 + ba];
            m  = fmaxf(m, nv);
            ns += nv;
            rs += u.p2.sps[t * 8 + ba];
        }
        float ncl = 0.f;
        #pragma unroll
        for (int k = 0; k < 16; k++) ncl += u.p2.snc[t * 16 + k];
        out[131072 + t] = m + ncl + rs;               // tot_ch
        out[131080 + t] = m;                          // max_nnz_ch
        out[131088 + t] = ncl;                        // num_col_ch
        out[131096 + t] = rs;                         // num_row_ch
        out[131168 + t] = ns / rs / ncl;              // col_density_ch
    }
    if (t == 64) out[131176] = u.p2.ssel;             // num_row_sel

    // reset barrier flags for the next graph replay
    __syncthreads();
    if (t < 128) g_flag[t] = 0;
}

// ---------------------------------------------------------------------------
extern "C" void kernel_launch(void* const* d_in, const int* in_sizes, int n_in,
                              void* d_out, int out_size)
{
    const float* W = (const float*)d_in[0];   // [2048, 64]
    const float* D = (const float*)d_in[1];   // [2048, 1024]
    const float* G = (const float*)d_in[2];   // [2048, 64]
    // d_in[3] = i, unused by the math
    float* out = (float*)d_out;

    k_all<<<NB, NT>>>(W, D, G, out);
}

// round 11
// speedup vs baseline: 1.6589x; 1.6589x over previous
#include <cuda_runtime.h>
#include <math.h>
#include <stdint.h>

// Problem constants
#define R_    2048
#define C_    1024
#define NCH   8

#define NRG   32                // row-groups (clusters)
#define NCL   8                 // CTAs per cluster
#define NK1   (NRG * NCL)       // 256 CTAs
#define NK3   136               // 128 colch blocks + 8 nnz/psum blocks

// Scratch (no allocations allowed -> device globals)
__device__ float g_Lpart[NCL * NRG * 1024];  // [cq][rg][ch*128+c]  1MB
__device__ float g_pA[64 * NK1];             // [i][block256] partial sum_r P*s
__device__ float g_pB[64 * NK1];             // [i][block256] partial sum_r P
__device__ float g_pSel[NK1];                // per-block row-sel partials
__device__ float g_ncolB[NCH * 16];          // [ch][cq*2+half] colch partials
__device__ float g_nnz[64];                  // nnz_ch_ba
__device__ float g_psum[64];                 // sum_r P per (ch,ba)
__device__ float g_selv;                     // row-sel count
__device__ unsigned int g_count = 0;         // K2 ticket (self-resetting)

// ---- cluster helpers ----
__device__ __forceinline__ uint32_t smem_u32(const void* p) {
    uint32_t a;
    asm("{ .reg .u64 t; cvta.to.shared.u64 t, %1; cvt.u32.u64 %0, t; }"
        : "=r"(a) : "l"(p));
    return a;
}
__device__ __forceinline__ uint32_t mapa_rank(uint32_t a, int r) {
    uint32_t o;
    asm("mapa.shared::cluster.u32 %0, %1, %2;" : "=r"(o) : "r"(a), "r"(r));
    return o;
}
__device__ __forceinline__ float4 ldsc_v4(uint32_t a) {
    float4 v;
    asm volatile("ld.shared::cluster.v4.f32 {%0,%1,%2,%3}, [%4];"
                 : "=f"(v.x), "=f"(v.y), "=f"(v.z), "=f"(v.w) : "r"(a));
    return v;
}
__device__ __forceinline__ float ldsc_f32(uint32_t a) {
    float v;
    asm volatile("ld.shared::cluster.f32 %0, [%1];" : "=f"(v) : "r"(a));
    return v;
}
#define CLUSTER_SYNC() do { \
    asm volatile("barrier.cluster.arrive.aligned;" ::: "memory"); \
    asm volatile("barrier.cluster.wait.aligned;"   ::: "memory"); \
} while (0)

// ---------------------------------------------------------------------------
// K1: 256 CTAs (32 clusters x 8). CTA (rg, k): softmax for rows
// rg*64 + k*8 .. +8 (one row per warp); lq exchanged cluster-wide via DSMEM;
// then D column-quarter k streamed over all 64 cluster rows (R8 inner loop);
// Lpart + exact pA/pB/sel partials.
// ---------------------------------------------------------------------------
__global__ __launch_bounds__(256) __cluster_dims__(NCL, 1, 1)
void k1(const float* __restrict__ W,
        const float* __restrict__ D,
        const float* __restrict__ G,
        float* __restrict__ out)
{
    __shared__ float  slq_mine[8][NCH];   // my 8 rows' lq
    __shared__ float  slq[64][NCH];       // gathered: all 64 cluster rows
    __shared__ float  sP[8][64];          // my 8 rows' P
    __shared__ float  sds[64];            // my quarter's row sums (64 rows)
    __shared__ float  sdsq[8][NCL];       // [my row j][quarter kk]
    __shared__ float  ss[8];              // full s[r] for my rows
    __shared__ float  sSel[8];
    __shared__ float4 sacc[8][256];       // 32KB cross-warp acc buffer

    const int t    = threadIdx.x;
    const int wid  = t >> 5;              // 0..7
    const int lane = t & 31;
    const int bid  = blockIdx.x;
    const int k    = bid & 7;             // cluster rank / column quarter
    const int rg   = bid >> 3;
    const int r0   = rg * 64;

    // ---- Stage A: softmax, warp w -> global row r0 + k*8 + w ----
    {
        const int r = r0 + k * 8 + wid;
        const float2* W2 = reinterpret_cast<const float2*>(W);
        const float2* G2 = reinterpret_cast<const float2*>(G);
        float2 w  = W2[r * 32 + lane];
        float2 gv = G2[r * 32 + lane];
        float e0 = w.x + gv.x;
        float e1 = w.y + gv.y;

        float m = fmaxf(e0, e1);
        #pragma unroll
        for (int o = 16; o > 0; o >>= 1)
            m = fmaxf(m, __shfl_xor_sync(0xFFFFFFFFu, m, o));

        float x0 = expf(e0 - m);
        float x1 = expf(e1 - m);
        float s  = x0 + x1;
        #pragma unroll
        for (int o = 16; o > 0; o >>= 1)
            s += __shfl_xor_sync(0xFFFFFFFFu, s, o);

        const float inv = 1.0f / s;       // == max(P): exp(0)=1 at the argmax
        const float p0  = x0 * inv;
        const float p1  = x1 * inv;

        reinterpret_cast<float2*>(out)[r * 32 + lane] = make_float2(p0, p1);
        sP[wid][2 * lane]     = p0;
        sP[wid][2 * lane + 1] = p1;

        float lq = log1pf(-p0) + log1pf(-p1);
        lq += __shfl_xor_sync(0xFFFFFFFFu, lq, 1);
        lq += __shfl_xor_sync(0xFFFFFFFFu, lq, 2);
        if ((lane & 3) == 0) slq_mine[wid][lane >> 2] = lq;
        if (lane == 0) sSel[wid] = (inv > 0.99f) ? 1.0f : 0.0f;
    }

    CLUSTER_SYNC();   // all CTAs' slq_mine visible cluster-wide

    // ---- gather all 64 rows' lq from owners via DSMEM ----
    if (t < 128) {
        const int rowi = t >> 1;          // 0..63
        const int part = t & 1;           // float4 half of the 8-ch row
        const int owner = rowi >> 3;
        uint32_t a  = smem_u32(&slq_mine[rowi & 7][0]) + part * 16;
        float4 v = ldsc_v4(mapa_rank(a, owner));
        *reinterpret_cast<float4*>(&slq[rowi][part * 4]) = v;
    }
    __syncthreads();

    // ---- Stage B: stream D quarter k over the 64 cluster rows ----
    float acc[NCH][4];
    #pragma unroll
    for (int ch = 0; ch < NCH; ch++)
        #pragma unroll
        for (int q = 0; q < 4; q++) acc[ch][q] = 0.f;
    float dsv[8];

    const float4* D4 = reinterpret_cast<const float4*>(D);
    #pragma unroll
    for (int j = 0; j < 8; j++) {
        const int rl = wid * 8 + j;
        float4 d = D4[(size_t)(r0 + rl) * 256 + k * 32 + lane];
        dsv[j] = (d.x + d.y) + (d.z + d.w);
        const float4 l0 = *reinterpret_cast<const float4*>(&slq[rl][0]);
        const float4 l1 = *reinterpret_cast<const float4*>(&slq[rl][4]);
        acc[0][0] = fmaf(d.x, l0.x, acc[0][0]); acc[0][1] = fmaf(d.y, l0.x, acc[0][1]);
        acc[0][2] = fmaf(d.z, l0.x, acc[0][2]); acc[0][3] = fmaf(d.w, l0.x, acc[0][3]);
        acc[1][0] = fmaf(d.x, l0.y, acc[1][0]); acc[1][1] = fmaf(d.y, l0.y, acc[1][1]);
        acc[1][2] = fmaf(d.z, l0.y, acc[1][2]); acc[1][3] = fmaf(d.w, l0.y, acc[1][3]);
        acc[2][0] = fmaf(d.x, l0.z, acc[2][0]); acc[2][1] = fmaf(d.y, l0.z, acc[2][1]);
        acc[2][2] = fmaf(d.z, l0.z, acc[2][2]); acc[2][3] = fmaf(d.w, l0.z, acc[2][3]);
        acc[3][0] = fmaf(d.x, l0.w, acc[3][0]); acc[3][1] = fmaf(d.y, l0.w, acc[3][1]);
        acc[3][2] = fmaf(d.z, l0.w, acc[3][2]); acc[3][3] = fmaf(d.w, l0.w, acc[3][3]);
        acc[4][0] = fmaf(d.x, l1.x, acc[4][0]); acc[4][1] = fmaf(d.y, l1.x, acc[4][1]);
        acc[4][2] = fmaf(d.z, l1.x, acc[4][2]); acc[4][3] = fmaf(d.w, l1.x, acc[4][3]);
        acc[5][0] = fmaf(d.x, l1.y, acc[5][0]); acc[5][1] = fmaf(d.y, l1.y, acc[5][1]);
        acc[5][2] = fmaf(d.z, l1.y, acc[5][2]); acc[5][3] = fmaf(d.w, l1.y, acc[5][3]);
        acc[6][0] = fmaf(d.x, l1.z, acc[6][0]); acc[6][1] = fmaf(d.y, l1.z, acc[6][1]);
        acc[6][2] = fmaf(d.z, l1.z, acc[6][2]); acc[6][3] = fmaf(d.w, l1.z, acc[6][3]);
        acc[7][0] = fmaf(d.x, l1.w, acc[7][0]); acc[7][1] = fmaf(d.y, l1.w, acc[7][1]);
        acc[7][2] = fmaf(d.z, l1.w, acc[7][2]); acc[7][3] = fmaf(d.w, l1.w, acc[7][3]);
    }

    // per-row quarter-sums (this quarter, all 64 rows)
    #pragma unroll
    for (int j = 0; j < 8; j++) {
        float v = dsv[j];
        #pragma unroll
        for (int o = 16; o > 0; o >>= 1)
            v += __shfl_xor_sync(0xFFFFFFFFu, v, o);
        if (lane == 0) sds[wid * 8 + j] = v;
    }

    // cross-warp acc reduction -> Lpart (R8 layout)
    #pragma unroll
    for (int ch = 0; ch < NCH; ch++)
        sacc[wid][ch * 32 + lane] =
            make_float4(acc[ch][0], acc[ch][1], acc[ch][2], acc[ch][3]);
    __syncthreads();
    {
        float4 s = sacc[0][t];
        #pragma unroll
        for (int g = 1; g < 8; g++) {
            float4 v = sacc[g][t];
            s.x += v.x; s.y += v.y; s.z += v.z; s.w += v.w;
        }
        reinterpret_cast<float4*>(g_Lpart)[(k * NRG + rg) * 256 + t] = s;
    }

    CLUSTER_SYNC();   // sds complete in every CTA

    // ---- gather full s[r] for MY 8 rows from the 8 quarters ----
    if (t < 64) {
        const int j  = t >> 3;            // my row 0..7
        const int kk = t & 7;             // quarter owner
        uint32_t a = smem_u32(&sds[k * 8 + j]);
        sdsq[j][kk] = ldsc_f32(mapa_rank(a, kk));
    }
    __syncthreads();
    if (t < 8) {
        float v = 0.f;
        #pragma unroll
        for (int kk = 0; kk < NCL; kk++) v += sdsq[t][kk];
        ss[t] = v;
    }
    __syncthreads();

    // ---- pA/pB/sel partials for my 8 rows ----
    if (t < 64) {
        float pa = 0.f, pb = 0.f;
        #pragma unroll
        for (int j = 0; j < 8; j++) {
            float p = sP[j][t];
            pb += p;
            pa  = fmaf(p, ss[j], pa);
        }
        g_pA[t * NK1 + bid] = pa;
        g_pB[t * NK1 + bid] = pb;
    }
    if (t == 0) {
        float v = 0.f;
        #pragma unroll
        for (int w2 = 0; w2 < 8; w2++) v += sSel[w2];
        g_pSel[bid] = v;
    }

    CLUSTER_SYNC();   // keep smem alive until all peers finished DSMEM reads
}

// ---------------------------------------------------------------------------
// K2: 136 blocks x 256 thr (R8's fastest-measured second kernel).
//  Blocks 0..127: colch. Block (cq, ch, half): 64 outputs, 32 partials each.
//  Blocks 128..135: nnz/psum/sel over 256 partials.
//  Last-ticket block finalizes all scalars.
// Output layout: P[131072] | tot[8] | max_nnz[8] | num_col[8] | num_row[8] |
//                nnz_ch_ba[64] | col_density[8] | num_row_sel[1]
// ---------------------------------------------------------------------------
__global__ __launch_bounds__(256) void k2_final(float* __restrict__ out)
{
    const int b    = blockIdx.x;
    const int t    = threadIdx.x;
    const int lane = t & 31;
    const int wid  = t >> 5;

    if (b < 128) {
        // ---- colch ----
        const int cq   = b >> 4;
        const int ch   = (b & 15) >> 1;
        const int half = b & 1;
        const int cl   = t & 63;
        const int pg   = t >> 6;            // 0..3

        const float* base = g_Lpart + (size_t)(cq * NRG + pg * 8) * 1024
                          + ch * 128 + half * 64 + cl;
        float a0 = base[0 * 1024], a1 = base[1 * 1024];
        float a2 = base[2 * 1024], a3 = base[3 * 1024];
        float a4 = base[4 * 1024], a5 = base[5 * 1024];
        float a6 = base[6 * 1024], a7 = base[7 * 1024];
        __shared__ float red[4][64];
        red[pg][cl] = ((a0 + a1) + (a2 + a3)) + ((a4 + a5) + (a6 + a7));
        __syncthreads();

        __shared__ float cs[2];
        if (t < 64) {
            float L = (red[0][t] + red[1][t]) + (red[2][t] + red[3][t]);
            float colch = 1.0f - expf(L);
            #pragma unroll
            for (int o = 16; o > 0; o >>= 1)
                colch += __shfl_xor_sync(0xFFFFFFFFu, colch, o);
            if (lane == 0) cs[t >> 5] = colch;
        }
        __syncthreads();
        if (t == 0) g_ncolB[ch * 16 + cq * 2 + half] = cs[0] + cs[1];
    } else {
        // ---- nnz / psum: 8 blocks x 8 warps = 64 outputs ----
        const int i = (b - 128) * 8 + wid;
        float an = 0.f, ap = 0.f;
        #pragma unroll
        for (int kk = 0; kk < 8; kk++) {
            an += g_pA[i * NK1 + lane + 32 * kk];
            ap += g_pB[i * NK1 + lane + 32 * kk];
        }
        #pragma unroll
        for (int o = 16; o > 0; o >>= 1) {
            an += __shfl_xor_sync(0xFFFFFFFFu, an, o);
            ap += __shfl_xor_sync(0xFFFFFFFFu, ap, o);
        }
        if (lane == 0) { g_nnz[i] = an; g_psum[i] = ap; }

        if (b == 128 && wid == 0) {          // sel: 256 partials
            float v = 0.f;
            #pragma unroll
            for (int kk = 0; kk < 8; kk++) v += g_pSel[lane + 32 * kk];
            #pragma unroll
            for (int o = 16; o > 0; o >>= 1)
                v += __shfl_xor_sync(0xFFFFFFFFu, v, o);
            if (lane == 0) g_selv = v;
        }
    }

    // ---- completion ticket: last block finalizes ----
    __shared__ int isLast;
    __threadfence();
    if (t == 0) {
        unsigned int old = atomicAdd(&g_count, 1u);
        isLast = (old == NK3 - 1) ? 1 : 0;
        if (isLast) g_count = 0;             // reset for next graph replay
    }
    __syncthreads();
    if (!isLast) return;
    __threadfence();                          // acquire other blocks' writes

    __shared__ float snn[64], sps[64], snc[128];
    if (t < 64)             { snn[t] = g_nnz[t]; sps[t] = g_psum[t]; }
    if (t >= 64 && t < 192)   snc[t - 64] = g_ncolB[t - 64];
    __syncthreads();

    if (t < 64) out[131104 + t] = snn[t];     // nnz_ch_ba

    if (t < NCH) {
        float m = -1e30f, ns = 0.f, rs = 0.f;
        #pragma unroll
        for (int ba = 0; ba < 8; ba++) {
            float nv = snn[t * 8 + ba];
            m  = fmaxf(m, nv);
            ns += nv;
            rs += sps[t * 8 + ba];
        }
        float ncl = 0.f;
        #pragma unroll
        for (int kk = 0; kk < 16; kk++) ncl += snc[t * 16 + kk];
        out[131072 + t] = m + ncl + rs;       // tot_ch
        out[131080 + t] = m;                  // max_nnz_ch
        out[131088 + t] = ncl;                // num_col_ch
        out[131096 + t] = rs;                 // num_row_ch
        out[131168 + t] = ns / rs / ncl;      // col_density_ch
    }
    if (t == 64) out[131176] = g_selv;        // num_row_sel
}

// ---------------------------------------------------------------------------
extern "C" void kernel_launch(void* const* d_in, const int* in_sizes, int n_in,
                              void* d_out, int out_size)
{
    const float* W = (const float*)d_in[0];   // [2048, 64]
    const float* D = (const float*)d_in[1];   // [2048, 1024]
    const float* G = (const float*)d_in[2];   // [2048, 64]
    // d_in[3] = i, unused by the math
    float* out = (float*)d_out;

    k1<<<NK1, 256>>>(W, D, G, out);
    k2_final<<<NK3, 256>>>(out);
}